// round 1
// baseline (speedup 1.0000x reference)
#include <cuda_runtime.h>
#include <math.h>

#define V  50257
#define H  1024
#define L  2048
#define ML 2048

// ---------------- scratch (device globals; no allocations allowed) ----------------
__device__ float g_attn_logits[ML];
__device__ float g_attn_weights[ML];
__device__ float g_attn_applied[H];
__device__ float g_rnn_in[H];
__device__ float g_gi[3 * H];
__device__ float g_gh[3 * H];
__device__ float g_hnew[H];
__device__ float g_score_g[V];
__device__ float g_score_c[L];
__device__ float g_coef[L];
__device__ float g_smax;
__device__ float g_sinv;

// ---------------- reduction helpers ----------------
__device__ __forceinline__ float block_reduce_max(float v, float* sred) {
    #pragma unroll
    for (int o = 16; o; o >>= 1) v = fmaxf(v, __shfl_xor_sync(0xffffffffu, v, o));
    int w = threadIdx.x >> 5;
    if ((threadIdx.x & 31) == 0) sred[w] = v;
    __syncthreads();
    int nw = (blockDim.x + 31) >> 5;
    if (threadIdx.x < 32) {
        float x = (threadIdx.x < nw) ? sred[threadIdx.x] : -1e30f;
        #pragma unroll
        for (int o = 16; o; o >>= 1) x = fmaxf(x, __shfl_xor_sync(0xffffffffu, x, o));
        if (threadIdx.x == 0) sred[0] = x;
    }
    __syncthreads();
    float r = sred[0];
    __syncthreads();
    return r;
}

__device__ __forceinline__ float block_reduce_sum(float v, float* sred) {
    #pragma unroll
    for (int o = 16; o; o >>= 1) v += __shfl_xor_sync(0xffffffffu, v, o);
    int w = threadIdx.x >> 5;
    if ((threadIdx.x & 31) == 0) sred[w] = v;
    __syncthreads();
    int nw = (blockDim.x + 31) >> 5;
    if (threadIdx.x < 32) {
        float x = (threadIdx.x < nw) ? sred[threadIdx.x] : 0.f;
        #pragma unroll
        for (int o = 16; o; o >>= 1) x += __shfl_xor_sync(0xffffffffu, x, o);
        if (threadIdx.x == 0) sred[0] = x;
    }
    __syncthreads();
    float r = sred[0];
    __syncthreads();
    return r;
}

__device__ __forceinline__ float warp_reduce_sum(float v) {
    #pragma unroll
    for (int o = 16; o; o >>= 1) v += __shfl_down_sync(0xffffffffu, v, o);
    return v;
}

// ---------------- kernels ----------------

// zero the atomic-accumulated scratch buffers
__global__ void k_init() {
    int i = blockIdx.x * blockDim.x + threadIdx.x;
    if (i < H) g_attn_applied[i] = 0.f;
    if (i < L) g_score_c[i] = 0.f;
}

// attn_logits[m] = [emb0, h0] . W_attn_w[m] + b_attn_w[m]   (ML rows, 2H dot)
__global__ void k_attn_logits(const int* __restrict__ din_p,
                              const float* __restrict__ emb,
                              const float* __restrict__ h0,
                              const float* __restrict__ Ww,
                              const float* __restrict__ bw) {
    int row  = (blockIdx.x * blockDim.x + threadIdx.x) >> 5;
    int lane = threadIdx.x & 31;
    if (row >= ML) return;
    const float4* w4 = (const float4*)(Ww + (size_t)row * (2 * H));
    const float4* e4 = (const float4*)(emb + (size_t)din_p[0] * H);
    const float4* h4 = (const float4*)h0;
    float acc = 0.f;
    #pragma unroll
    for (int q = lane; q < 256; q += 32) {
        float4 a = w4[q]; float4 x = e4[q];
        acc += a.x * x.x + a.y * x.y + a.z * x.z + a.w * x.w;
    }
    #pragma unroll
    for (int q = lane; q < 256; q += 32) {
        float4 a = w4[256 + q]; float4 x = h4[q];
        acc += a.x * x.x + a.y * x.y + a.z * x.z + a.w * x.w;
    }
    acc = warp_reduce_sum(acc);
    if (lane == 0) g_attn_logits[row] = acc + bw[row];
}

// softmax over ML=2048 (one block, 1024 threads)
__global__ void k_softmax_ml() {
    __shared__ float sred[32];
    int t = threadIdx.x;
    float a = g_attn_logits[t];
    float b = g_attn_logits[t + 1024];
    float m = block_reduce_max(fmaxf(a, b), sred);
    float e1 = expf(a - m);
    float e2 = expf(b - m);
    float s = block_reduce_sum(e1 + e2, sred);
    float inv = 1.f / s;
    g_attn_weights[t]        = e1 * inv;
    g_attn_weights[t + 1024] = e2 * inv;
}

// attn_applied[j] = sum_i attn_weights[i] * E[i][j]  (32 blocks x 1024 thr, 64 rows/block)
__global__ void k_attn_applied(const float* __restrict__ E) {
    __shared__ float w[64];
    int r0 = blockIdx.x * 64;
    if (threadIdx.x < 64) w[threadIdx.x] = g_attn_weights[r0 + threadIdx.x];
    __syncthreads();
    int j = threadIdx.x;
    float acc = 0.f;
    #pragma unroll 4
    for (int i = 0; i < 64; i++)
        acc += w[i] * E[(size_t)(r0 + i) * H + j];
    atomicAdd(&g_attn_applied[j], acc);
}

// rnn_in[j] = relu([emb0, attn_applied] . W_attn_u[j] + b_attn_u[j])  (H rows, 2H dot)
__global__ void k_rnn_in(const int* __restrict__ din_p,
                         const float* __restrict__ emb,
                         const float* __restrict__ Wu,
                         const float* __restrict__ bu) {
    int row  = (blockIdx.x * blockDim.x + threadIdx.x) >> 5;
    int lane = threadIdx.x & 31;
    if (row >= H) return;
    const float4* w4 = (const float4*)(Wu + (size_t)row * (2 * H));
    const float4* e4 = (const float4*)(emb + (size_t)din_p[0] * H);
    const float4* a4 = (const float4*)g_attn_applied;
    float acc = 0.f;
    #pragma unroll
    for (int q = lane; q < 256; q += 32) {
        float4 a = w4[q]; float4 x = e4[q];
        acc += a.x * x.x + a.y * x.y + a.z * x.z + a.w * x.w;
    }
    #pragma unroll
    for (int q = lane; q < 256; q += 32) {
        float4 a = w4[256 + q]; float4 x = a4[q];
        acc += a.x * x.x + a.y * x.y + a.z * x.z + a.w * x.w;
    }
    acc = warp_reduce_sum(acc);
    if (lane == 0) g_rnn_in[row] = fmaxf(acc + bu[row], 0.f);
}

// gi = W_ih @ rnn_in + b_ih ; gh = W_hh @ h0 + b_hh  (6144 warp-rows, 1024 dot)
__global__ void k_gi_gh(const float* __restrict__ Wih, const float* __restrict__ bih,
                        const float* __restrict__ Whh, const float* __restrict__ bhh,
                        const float* __restrict__ h0) {
    int g    = (blockIdx.x * blockDim.x + threadIdx.x) >> 5;
    int lane = threadIdx.x & 31;
    if (g >= 6 * H) return;
    const float4* w4;
    const float4* x4;
    float bb;
    float* outp;
    if (g < 3 * H) {
        w4 = (const float4*)(Wih + (size_t)g * H);
        x4 = (const float4*)g_rnn_in;
        bb = bih[g];
        outp = &g_gi[g];
    } else {
        int r = g - 3 * H;
        w4 = (const float4*)(Whh + (size_t)r * H);
        x4 = (const float4*)h0;
        bb = bhh[r];
        outp = &g_gh[r];
    }
    float acc = 0.f;
    #pragma unroll
    for (int q = lane; q < 256; q += 32) {
        float4 a = w4[q]; float4 x = x4[q];
        acc += a.x * x.x + a.y * x.y + a.z * x.z + a.w * x.w;
    }
    acc = warp_reduce_sum(acc);
    if (lane == 0) *outp = acc + bb;
}

// GRU combine; writes h_new and the final_hidden output segment
__global__ void k_gru(const float* __restrict__ h0, float* __restrict__ out) {
    int t = threadIdx.x;
    float r = 1.f / (1.f + expf(-(g_gi[t] + g_gh[t])));
    float z = 1.f / (1.f + expf(-(g_gi[H + t] + g_gh[H + t])));
    float n = tanhf(g_gi[2 * H + t] + r * g_gh[2 * H + t]);
    float h = (1.f - z) * n + z * h0[t];
    g_hnew[t] = h;
    out[V + t] = h;  // final_hidden
}

// score_g[v] = h_new . W_gen[v] + b_gen[v]  (V warp-rows, 1024 dot) — 206 MB stream
__global__ void k_score_g(const float* __restrict__ Wg, const float* __restrict__ bg) {
    int row  = (blockIdx.x * blockDim.x + threadIdx.x) >> 5;
    int lane = threadIdx.x & 31;
    if (row >= V) return;
    const float4* w4 = (const float4*)(Wg + (size_t)row * H);
    const float4* h4 = (const float4*)g_hnew;
    float acc = 0.f;
    #pragma unroll
    for (int q = lane; q < 256; q += 32) {
        float4 a = w4[q]; float4 x = h4[q];
        acc += a.x * x.x + a.y * x.y + a.z * x.z + a.w * x.w;
    }
    acc = warp_reduce_sum(acc);
    if (lane == 0) g_score_g[row] = acc + bg[row];
}

// score_c[i] = sum_j tanh(E[i].W_copy[j] + b_copy[j]) * h0[j]
// Tiled NT SGEMM (both operands K-contiguous), fused tanh*h0 reduction epilogue.
// BM=BN=128, BK=16, 256 threads, 8x8 per thread. Grid (N/128=8, M/128=16)=128 blocks.
__global__ __launch_bounds__(256) void k_score_c_gemm(
    const float* __restrict__ A,     // E: 2048 x 1024
    const float* __restrict__ B,     // W_copy: 1024 x 1024
    const float* __restrict__ bias,  // b_copy
    const float* __restrict__ h0) {
    const int BK = 16;
    __shared__ float As[BK][128];
    __shared__ float Bs[BK][128];
    int tid = threadIdx.x;
    int tx = tid & 15;
    int ty = tid >> 4;
    int rowBase = blockIdx.y * 128;
    int colBase = blockIdx.x * 128;
    float acc[8][8] = {};
    for (int kt = 0; kt < 1024; kt += BK) {
        #pragma unroll
        for (int p = 0; p < 2; p++) {
            int idx = tid + p * 256;
            int r = idx >> 2;
            int kq = idx & 3;
            float4 v = *(const float4*)(A + (size_t)(rowBase + r) * 1024 + kt + kq * 4);
            As[kq * 4 + 0][r] = v.x; As[kq * 4 + 1][r] = v.y;
            As[kq * 4 + 2][r] = v.z; As[kq * 4 + 3][r] = v.w;
        }
        #pragma unroll
        for (int p = 0; p < 2; p++) {
            int idx = tid + p * 256;
            int r = idx >> 2;
            int kq = idx & 3;
            float4 v = *(const float4*)(B + (size_t)(colBase + r) * 1024 + kt + kq * 4);
            Bs[kq * 4 + 0][r] = v.x; Bs[kq * 4 + 1][r] = v.y;
            Bs[kq * 4 + 2][r] = v.z; Bs[kq * 4 + 3][r] = v.w;
        }
        __syncthreads();
        #pragma unroll
        for (int kk = 0; kk < BK; kk++) {
            float a[8], b[8];
            #pragma unroll
            for (int i = 0; i < 8; i++) a[i] = As[kk][ty * 8 + i];
            #pragma unroll
            for (int j = 0; j < 8; j++) b[j] = Bs[kk][tx * 8 + j];
            #pragma unroll
            for (int i = 0; i < 8; i++)
                #pragma unroll
                for (int j = 0; j < 8; j++)
                    acc[i][j] = fmaf(a[i], b[j], acc[i][j]);
        }
        __syncthreads();
    }
    // epilogue: partial[i] = sum_j tanh(acc+bias)*h0, reduce over tx, atomicAdd
    __shared__ float red[128][17];
    float hv[8], bv[8];
    #pragma unroll
    for (int j = 0; j < 8; j++) {
        int c = colBase + tx * 8 + j;
        hv[j] = h0[c];
        bv[j] = bias[c];
    }
    #pragma unroll
    for (int i = 0; i < 8; i++) {
        float s = 0.f;
        #pragma unroll
        for (int j = 0; j < 8; j++) s += tanhf(acc[i][j] + bv[j]) * hv[j];
        red[ty * 8 + i][tx] = s;
    }
    __syncthreads();
    if (tid < 128) {
        float s = 0.f;
        #pragma unroll
        for (int x = 0; x < 16; x++) s += red[tid][x];
        atomicAdd(&g_score_c[rowBase + tid], s);
    }
}

// global softmax scalars over concat(score_g[V], score_c[L]) — one block
__global__ void k_softmax_all() {
    __shared__ float sred[32];
    int t = threadIdx.x;
    float m = -1e30f;
    for (int i = t; i < V; i += 1024) m = fmaxf(m, g_score_g[i]);
    for (int i = t; i < L; i += 1024) m = fmaxf(m, g_score_c[i]);
    m = block_reduce_max(m, sred);
    float s = 0.f;
    for (int i = t; i < V; i += 1024) s += expf(g_score_g[i] - m);
    for (int i = t; i < L; i += 1024) s += expf(g_score_c[i] - m);
    s = block_reduce_sum(s, sred);
    if (t == 0) { g_smax = m; g_sinv = 1.f / s; }
}

// final_output[v] = prob_g[v]
__global__ void k_out_g(float* __restrict__ out) {
    int i = blockIdx.x * blockDim.x + threadIdx.x;
    if (i < V) out[i] = expf(g_score_g[i] - g_smax) * g_sinv;
}

// prob_c scatter-add into final_output; coef for final_weights
__global__ void k_out_c(const int* __restrict__ iv, const int* __restrict__ din_p,
                        float* __restrict__ out) {
    int i = blockIdx.x * blockDim.x + threadIdx.x;
    if (i >= L) return;
    float pc = expf(g_score_c[i] - g_smax) * g_sinv;
    int id = iv[i];
    atomicAdd(&out[id], pc);
    g_coef[i] = (id == din_p[0]) ? pc : 0.f;
}

// final_weights[j] = sum_i coef[i] * E[i][j]  (coef is ~all zeros; scan + sparse rows)
__global__ void k_fw(const float* __restrict__ E, float* __restrict__ out) {
    __shared__ float cf[L];
    int t = threadIdx.x;
    for (int i = t; i < L; i += 1024) cf[i] = g_coef[i];
    __syncthreads();
    float acc = 0.f;
    for (int i = 0; i < L; i++) {
        float c = cf[i];
        if (c != 0.f) acc += c * E[(size_t)i * H + t];
    }
    out[V + H + t] = acc;  // final_weights
}

// ---------------- launcher ----------------
extern "C" void kernel_launch(void* const* d_in, const int* in_sizes, int n_in,
                              void* d_out, int out_size) {
    const int*   din  = (const int*)d_in[0];
    const float* h0   = (const float*)d_in[1];
    const float* E    = (const float*)d_in[2];
    const int*   iv   = (const int*)d_in[3];
    const float* emb  = (const float*)d_in[4];
    const float* Ww   = (const float*)d_in[5];
    const float* bw   = (const float*)d_in[6];
    const float* Wu   = (const float*)d_in[7];
    const float* bu   = (const float*)d_in[8];
    const float* Wih  = (const float*)d_in[9];
    const float* bih  = (const float*)d_in[10];
    const float* Whh  = (const float*)d_in[11];
    const float* bhh  = (const float*)d_in[12];
    const float* Wc   = (const float*)d_in[13];
    const float* bc   = (const float*)d_in[14];
    const float* Wg   = (const float*)d_in[15];
    const float* bg   = (const float*)d_in[16];
    float* out = (float*)d_out;

    k_init<<<8, 256>>>();
    k_attn_logits<<<(ML * 32) / 256, 256>>>(din, emb, h0, Ww, bw);
    k_softmax_ml<<<1, 1024>>>();
    k_attn_applied<<<32, 1024>>>(E);
    k_rnn_in<<<(H * 32) / 256, 256>>>(din, emb, Wu, bu);
    k_gi_gh<<<(6 * H * 32) / 256, 256>>>(Wih, bih, Whh, bhh, h0);
    k_gru<<<1, 1024>>>(h0, out);
    k_score_g<<<(V + 7) / 8, 256>>>(Wg, bg);
    {
        dim3 grid(1024 / 128, 2048 / 128);  // (8, 16)
        k_score_c_gemm<<<grid, 256>>>(E, Wc, bc, h0);
    }
    k_softmax_all<<<1, 1024>>>();
    k_out_g<<<(V + 255) / 256, 256>>>(out);
    k_out_c<<<L / 256, 256>>>(iv, din, out);
    k_fw<<<1, 1024>>>(E, out);
}

// round 2
// speedup vs baseline: 1.2738x; 1.2738x over previous
#include <cuda_runtime.h>
#include <math.h>

#define V  50257
#define H  1024
#define L  2048
#define ML 2048

typedef unsigned long long ull;

// ---------------- scratch (device globals; no allocations allowed) ----------------
__device__ float g_attn_logits[ML];
__device__ float g_attn_weights[ML];
__device__ float g_attn_applied[H];
__device__ float g_rnn_in[H];
__device__ float g_gi[3 * H];
__device__ float g_gh[3 * H];
__device__ float g_hnew[H];
__device__ float g_score_g[V];
__device__ float g_score_c[L];
__device__ unsigned g_maxkey;
__device__ float g_ssum;
__device__ int   g_nmatch;
__device__ int   g_midx[L];
__device__ float g_mpc[L];

// ---------------- helpers ----------------
__device__ __forceinline__ unsigned fkey(float f) {
    unsigned b = __float_as_uint(f);
    return (b & 0x80000000u) ? ~b : (b | 0x80000000u);
}
__device__ __forceinline__ float funkey(unsigned k) {
    return (k & 0x80000000u) ? __uint_as_float(k ^ 0x80000000u)
                             : __uint_as_float(~k);
}

__device__ __forceinline__ void ffma2(ull& d, ull a, ull b) {
    asm("fma.rn.f32x2 %0, %1, %2, %0;" : "+l"(d) : "l"(a), "l"(b));
}
__device__ __forceinline__ ull pack2(float lo, float hi) {
    ull r; asm("mov.b64 %0, {%1, %2};" : "=l"(r) : "f"(lo), "f"(hi)); return r;
}
__device__ __forceinline__ void unpack2(ull v, float& lo, float& hi) {
    asm("mov.b64 {%0, %1}, %2;" : "=f"(lo), "=f"(hi) : "l"(v));
}

__device__ __forceinline__ float block_reduce_max(float v, float* sred) {
    #pragma unroll
    for (int o = 16; o; o >>= 1) v = fmaxf(v, __shfl_xor_sync(0xffffffffu, v, o));
    int w = threadIdx.x >> 5;
    if ((threadIdx.x & 31) == 0) sred[w] = v;
    __syncthreads();
    int nw = (blockDim.x + 31) >> 5;
    if (threadIdx.x < 32) {
        float x = (threadIdx.x < nw) ? sred[threadIdx.x] : -1e30f;
        #pragma unroll
        for (int o = 16; o; o >>= 1) x = fmaxf(x, __shfl_xor_sync(0xffffffffu, x, o));
        if (threadIdx.x == 0) sred[0] = x;
    }
    __syncthreads();
    float r = sred[0];
    __syncthreads();
    return r;
}

__device__ __forceinline__ float block_reduce_sum(float v, float* sred) {
    #pragma unroll
    for (int o = 16; o; o >>= 1) v += __shfl_xor_sync(0xffffffffu, v, o);
    int w = threadIdx.x >> 5;
    if ((threadIdx.x & 31) == 0) sred[w] = v;
    __syncthreads();
    int nw = (blockDim.x + 31) >> 5;
    if (threadIdx.x < 32) {
        float x = (threadIdx.x < nw) ? sred[threadIdx.x] : 0.f;
        #pragma unroll
        for (int o = 16; o; o >>= 1) x += __shfl_xor_sync(0xffffffffu, x, o);
        if (threadIdx.x == 0) sred[0] = x;
    }
    __syncthreads();
    float r = sred[0];
    __syncthreads();
    return r;
}

__device__ __forceinline__ float warp_reduce_sum(float v) {
    #pragma unroll
    for (int o = 16; o; o >>= 1) v += __shfl_down_sync(0xffffffffu, v, o);
    return v;
}

// ---------------- kernels ----------------

__global__ void k_init() {
    int i = blockIdx.x * blockDim.x + threadIdx.x;
    if (i < H) g_attn_applied[i] = 0.f;
    if (i < L) g_score_c[i] = 0.f;
    if (i == 0) { g_maxkey = 0u; g_ssum = 0.f; g_nmatch = 0; }
}

// attn_logits[m] = [emb0, h0] . W_attn_w[m] + b_attn_w[m]
__global__ void k_attn_logits(const int* __restrict__ din_p,
                              const float* __restrict__ emb,
                              const float* __restrict__ h0,
                              const float* __restrict__ Ww,
                              const float* __restrict__ bw) {
    int row  = (blockIdx.x * blockDim.x + threadIdx.x) >> 5;
    int lane = threadIdx.x & 31;
    if (row >= ML) return;
    const float4* w4 = (const float4*)(Ww + (size_t)row * (2 * H));
    const float4* e4 = (const float4*)(emb + (size_t)din_p[0] * H);
    const float4* h4 = (const float4*)h0;
    float acc = 0.f;
    #pragma unroll
    for (int q = lane; q < 256; q += 32) {
        float4 a = w4[q]; float4 x = e4[q];
        acc += a.x * x.x + a.y * x.y + a.z * x.z + a.w * x.w;
    }
    #pragma unroll
    for (int q = lane; q < 256; q += 32) {
        float4 a = w4[256 + q]; float4 x = h4[q];
        acc += a.x * x.x + a.y * x.y + a.z * x.z + a.w * x.w;
    }
    acc = warp_reduce_sum(acc);
    if (lane == 0) g_attn_logits[row] = acc + bw[row];
}

// softmax over ML=2048 (one block, 1024 threads)
__global__ void k_softmax_ml() {
    __shared__ float sred[32];
    int t = threadIdx.x;
    float a = g_attn_logits[t];
    float b = g_attn_logits[t + 1024];
    float m = block_reduce_max(fmaxf(a, b), sred);
    float e1 = expf(a - m);
    float e2 = expf(b - m);
    float s = block_reduce_sum(e1 + e2, sred);
    float inv = 1.f / s;
    g_attn_weights[t]        = e1 * inv;
    g_attn_weights[t + 1024] = e2 * inv;
}

// attn_applied[j] += sum over 16 rows: 128 blocks, high MLP
__global__ void k_attn_applied(const float* __restrict__ E) {
    __shared__ float w[16];
    int r0 = blockIdx.x * 16;
    if (threadIdx.x < 16) w[threadIdx.x] = g_attn_weights[r0 + threadIdx.x];
    __syncthreads();
    int j = threadIdx.x;  // 1024 == H
    float acc = 0.f;
    #pragma unroll
    for (int i = 0; i < 16; i++)
        acc += w[i] * E[(size_t)(r0 + i) * H + j];
    atomicAdd(&g_attn_applied[j], acc);
}

// rnn_in[j] = relu([emb0, attn_applied] . W_attn_u[j] + b_attn_u[j])
__global__ void k_rnn_in(const int* __restrict__ din_p,
                         const float* __restrict__ emb,
                         const float* __restrict__ Wu,
                         const float* __restrict__ bu) {
    int row  = (blockIdx.x * blockDim.x + threadIdx.x) >> 5;
    int lane = threadIdx.x & 31;
    if (row >= H) return;
    const float4* w4 = (const float4*)(Wu + (size_t)row * (2 * H));
    const float4* e4 = (const float4*)(emb + (size_t)din_p[0] * H);
    const float4* a4 = (const float4*)g_attn_applied;
    float acc = 0.f;
    #pragma unroll
    for (int q = lane; q < 256; q += 32) {
        float4 a = w4[q]; float4 x = e4[q];
        acc += a.x * x.x + a.y * x.y + a.z * x.z + a.w * x.w;
    }
    #pragma unroll
    for (int q = lane; q < 256; q += 32) {
        float4 a = w4[256 + q]; float4 x = a4[q];
        acc += a.x * x.x + a.y * x.y + a.z * x.z + a.w * x.w;
    }
    acc = warp_reduce_sum(acc);
    if (lane == 0) g_rnn_in[row] = fmaxf(acc + bu[row], 0.f);
}

// gi = W_ih @ rnn_in + b_ih ; gh = W_hh @ h0 + b_hh
__global__ void k_gi_gh(const float* __restrict__ Wih, const float* __restrict__ bih,
                        const float* __restrict__ Whh, const float* __restrict__ bhh,
                        const float* __restrict__ h0) {
    int g    = (blockIdx.x * blockDim.x + threadIdx.x) >> 5;
    int lane = threadIdx.x & 31;
    if (g >= 6 * H) return;
    const float4* w4;
    const float4* x4;
    float bb;
    float* outp;
    if (g < 3 * H) {
        w4 = (const float4*)(Wih + (size_t)g * H);
        x4 = (const float4*)g_rnn_in;
        bb = bih[g];
        outp = &g_gi[g];
    } else {
        int r = g - 3 * H;
        w4 = (const float4*)(Whh + (size_t)r * H);
        x4 = (const float4*)h0;
        bb = bhh[r];
        outp = &g_gh[r];
    }
    float acc = 0.f;
    #pragma unroll
    for (int q = lane; q < 256; q += 32) {
        float4 a = w4[q]; float4 x = x4[q];
        acc += a.x * x.x + a.y * x.y + a.z * x.z + a.w * x.w;
    }
    acc = warp_reduce_sum(acc);
    if (lane == 0) *outp = acc + bb;
}

// GRU combine; writes h_new and final_hidden
__global__ void k_gru(const float* __restrict__ h0, float* __restrict__ out) {
    int t = threadIdx.x;
    float r = 1.f / (1.f + expf(-(g_gi[t] + g_gh[t])));
    float z = 1.f / (1.f + expf(-(g_gi[H + t] + g_gh[H + t])));
    float n = tanhf(g_gi[2 * H + t] + r * g_gh[2 * H + t]);
    float h = (1.f - z) * n + z * h0[t];
    g_hnew[t] = h;
    out[V + t] = h;
}

// score_g[v] = h_new . W_gen[v] + b_gen[v]  — 206 MB stream, warp per row
__global__ void k_score_g(const float* __restrict__ Wg, const float* __restrict__ bg) {
    int row  = (blockIdx.x * blockDim.x + threadIdx.x) >> 5;
    int lane = threadIdx.x & 31;
    if (row >= V) return;
    const float4* w4 = (const float4*)(Wg + (size_t)row * H);
    const float4* h4 = (const float4*)g_hnew;
    float acc = 0.f;
    #pragma unroll
    for (int q = lane; q < 256; q += 32) {
        float4 a = w4[q]; float4 x = h4[q];
        acc += a.x * x.x + a.y * x.y + a.z * x.z + a.w * x.w;
    }
    acc = warp_reduce_sum(acc);
    if (lane == 0) g_score_g[row] = acc + bg[row];
}

// score_c[i] = sum_j tanh(E[i].W_copy[j] + b_copy[j]) * h0[j]
// NT SGEMM, BM=BN=128, BK=16, 256 thr, 8x8/thread via packed fma.rn.f32x2,
// double-buffered smem with gmem prefetch. Fused tanh*h0 epilogue.
__global__ __launch_bounds__(256) void k_score_c_gemm(
    const float* __restrict__ A,     // E: 2048 x 1024 (row-major, K contiguous)
    const float* __restrict__ B,     // W_copy: 1024 x 1024 (row-major, K contiguous)
    const float* __restrict__ bias,  // b_copy
    const float* __restrict__ h0) {
    const int BK = 16;
    __shared__ float As[2][BK][128];
    __shared__ float Bs[2][BK][128];
    int tid = threadIdx.x;
    int tx = tid & 15;
    int ty = tid >> 4;
    int rowBase = blockIdx.y * 128;
    int colBase = blockIdx.x * 128;

    ull acc[8][4];
    #pragma unroll
    for (int i = 0; i < 8; i++)
        #pragma unroll
        for (int jj = 0; jj < 4; jj++) acc[i][jj] = 0ull;

    int ld_r[2], ld_kq[2];
    #pragma unroll
    for (int p = 0; p < 2; p++) {
        int idx = tid + p * 256;
        ld_r[p]  = idx >> 2;
        ld_kq[p] = idx & 3;
    }

    float4 pa[2], pb[2];
    // prologue: tile 0 loads
    #pragma unroll
    for (int p = 0; p < 2; p++) {
        pa[p] = *(const float4*)(A + (size_t)(rowBase + ld_r[p]) * 1024 + ld_kq[p] * 4);
        pb[p] = *(const float4*)(B + (size_t)(colBase + ld_r[p]) * 1024 + ld_kq[p] * 4);
    }
    #pragma unroll
    for (int p = 0; p < 2; p++) {
        As[0][ld_kq[p] * 4 + 0][ld_r[p]] = pa[p].x;
        As[0][ld_kq[p] * 4 + 1][ld_r[p]] = pa[p].y;
        As[0][ld_kq[p] * 4 + 2][ld_r[p]] = pa[p].z;
        As[0][ld_kq[p] * 4 + 3][ld_r[p]] = pa[p].w;
        Bs[0][ld_kq[p] * 4 + 0][ld_r[p]] = pb[p].x;
        Bs[0][ld_kq[p] * 4 + 1][ld_r[p]] = pb[p].y;
        Bs[0][ld_kq[p] * 4 + 2][ld_r[p]] = pb[p].z;
        Bs[0][ld_kq[p] * 4 + 3][ld_r[p]] = pb[p].w;
    }
    __syncthreads();

    for (int t = 0; t < 64; t++) {
        int cur = t & 1;
        if (t < 63) {
            int kt = (t + 1) * BK;
            #pragma unroll
            for (int p = 0; p < 2; p++) {
                pa[p] = *(const float4*)(A + (size_t)(rowBase + ld_r[p]) * 1024 + kt + ld_kq[p] * 4);
                pb[p] = *(const float4*)(B + (size_t)(colBase + ld_r[p]) * 1024 + kt + ld_kq[p] * 4);
            }
        }
        #pragma unroll
        for (int kk = 0; kk < BK; kk++) {
            ull ad[8];
            #pragma unroll
            for (int i = 0; i < 8; i++) {
                float av = As[cur][kk][ty * 8 + i];
                ad[i] = pack2(av, av);
            }
            ull b2[4];
            #pragma unroll
            for (int jj = 0; jj < 4; jj++)
                b2[jj] = *(const ull*)&Bs[cur][kk][tx * 8 + jj * 2];
            #pragma unroll
            for (int i = 0; i < 8; i++)
                #pragma unroll
                for (int jj = 0; jj < 4; jj++)
                    ffma2(acc[i][jj], ad[i], b2[jj]);
        }
        if (t < 63) {
            int nb = 1 - cur;
            #pragma unroll
            for (int p = 0; p < 2; p++) {
                As[nb][ld_kq[p] * 4 + 0][ld_r[p]] = pa[p].x;
                As[nb][ld_kq[p] * 4 + 1][ld_r[p]] = pa[p].y;
                As[nb][ld_kq[p] * 4 + 2][ld_r[p]] = pa[p].z;
                As[nb][ld_kq[p] * 4 + 3][ld_r[p]] = pa[p].w;
                Bs[nb][ld_kq[p] * 4 + 0][ld_r[p]] = pb[p].x;
                Bs[nb][ld_kq[p] * 4 + 1][ld_r[p]] = pb[p].y;
                Bs[nb][ld_kq[p] * 4 + 2][ld_r[p]] = pb[p].z;
                Bs[nb][ld_kq[p] * 4 + 3][ld_r[p]] = pb[p].w;
            }
            __syncthreads();
        }
    }

    // epilogue: s_i = sum_j tanh(acc+bias[j]) * h0[j]; reduce across tx; atomicAdd
    __shared__ float red[128][17];
    float hv[8], bv[8];
    #pragma unroll
    for (int j = 0; j < 8; j++) {
        int c = colBase + tx * 8 + j;
        hv[j] = h0[c];
        bv[j] = bias[c];
    }
    #pragma unroll
    for (int i = 0; i < 8; i++) {
        float s = 0.f;
        #pragma unroll
        for (int jj = 0; jj < 4; jj++) {
            float lo, hi;
            unpack2(acc[i][jj], lo, hi);
            s += tanhf(lo + bv[jj * 2])     * hv[jj * 2];
            s += tanhf(hi + bv[jj * 2 + 1]) * hv[jj * 2 + 1];
        }
        red[ty * 8 + i][tx] = s;
    }
    __syncthreads();
    if (tid < 128) {
        float s = 0.f;
        #pragma unroll
        for (int x = 0; x < 16; x++) s += red[tid][x];
        atomicAdd(&g_score_c[rowBase + tid], s);
    }
}

// global max over concat(score_g, score_c) — grid-wide, atomicMax on ordered key
__global__ void k_redmax() {
    __shared__ float sred[32];
    int stride = gridDim.x * blockDim.x;
    float m = -1e30f;
    for (int x = blockIdx.x * blockDim.x + threadIdx.x; x < V + L; x += stride) {
        float v = (x < V) ? g_score_g[x] : g_score_c[x - V];
        m = fmaxf(m, v);
    }
    m = block_reduce_max(m, sred);
    if (threadIdx.x == 0) atomicMax(&g_maxkey, fkey(m));
}

// global sum of exp(x - max) — grid-wide, atomicAdd
__global__ void k_redsum() {
    __shared__ float sred[32];
    float m = funkey(g_maxkey);
    int stride = gridDim.x * blockDim.x;
    float s = 0.f;
    for (int x = blockIdx.x * blockDim.x + threadIdx.x; x < V + L; x += stride) {
        float v = (x < V) ? g_score_g[x] : g_score_c[x - V];
        s += expf(v - m);
    }
    s = block_reduce_sum(s, sred);
    if (threadIdx.x == 0) atomicAdd(&g_ssum, s);
}

// final_output[v] = prob_g[v]
__global__ void k_out_g(float* __restrict__ out) {
    int i = blockIdx.x * blockDim.x + threadIdx.x;
    if (i >= V) return;
    float m = funkey(g_maxkey);
    out[i] = expf(g_score_g[i] - m) / g_ssum;
}

// prob_c scatter-add; compact matched rows for final_weights
__global__ void k_out_c(const int* __restrict__ iv, const int* __restrict__ din_p,
                        float* __restrict__ out) {
    int i = blockIdx.x * blockDim.x + threadIdx.x;
    if (i >= L) return;
    float m = funkey(g_maxkey);
    float pc = expf(g_score_c[i] - m) / g_ssum;
    int id = iv[i];
    atomicAdd(&out[id], pc);
    if (id == din_p[0]) {
        int p = atomicAdd(&g_nmatch, 1);
        g_midx[p] = i;
        g_mpc[p] = pc;
    }
}

// final_weights[j] = sum over compacted matches (usually 0 or 1 rows)
__global__ void k_fw(const float* __restrict__ E, float* __restrict__ out) {
    int t = threadIdx.x;  // 1024 == H
    int n = g_nmatch;
    float acc = 0.f;
    for (int p = 0; p < n; p++)
        acc += g_mpc[p] * E[(size_t)g_midx[p] * H + t];
    out[V + H + t] = acc;
}

// ---------------- launcher ----------------
extern "C" void kernel_launch(void* const* d_in, const int* in_sizes, int n_in,
                              void* d_out, int out_size) {
    const int*   din  = (const int*)d_in[0];
    const float* h0   = (const float*)d_in[1];
    const float* E    = (const float*)d_in[2];
    const int*   iv   = (const int*)d_in[3];
    const float* emb  = (const float*)d_in[4];
    const float* Ww   = (const float*)d_in[5];
    const float* bw   = (const float*)d_in[6];
    const float* Wu   = (const float*)d_in[7];
    const float* bu   = (const float*)d_in[8];
    const float* Wih  = (const float*)d_in[9];
    const float* bih  = (const float*)d_in[10];
    const float* Whh  = (const float*)d_in[11];
    const float* bhh  = (const float*)d_in[12];
    const float* Wc   = (const float*)d_in[13];
    const float* bc   = (const float*)d_in[14];
    const float* Wg   = (const float*)d_in[15];
    const float* bg   = (const float*)d_in[16];
    float* out = (float*)d_out;

    k_init<<<12, 256>>>();
    {
        dim3 grid(1024 / 128, 2048 / 128);  // (8, 16)
        k_score_c_gemm<<<grid, 256>>>(E, Wc, bc, h0);
    }
    k_attn_logits<<<(ML * 32) / 256, 256>>>(din, emb, h0, Ww, bw);
    k_softmax_ml<<<1, 1024>>>();
    k_attn_applied<<<128, 1024>>>(E);
    k_rnn_in<<<(H * 32) / 256, 256>>>(din, emb, Wu, bu);
    k_gi_gh<<<(6 * H * 32) / 256, 256>>>(Wih, bih, Whh, bhh, h0);
    k_gru<<<1, 1024>>>(h0, out);
    k_score_g<<<(V + 7) / 8, 256>>>(Wg, bg);
    k_redmax<<<52, 1024>>>();
    k_redsum<<<52, 1024>>>();
    k_out_g<<<(V + 255) / 256, 256>>>(out);
    k_out_c<<<L / 256, 256>>>(iv, din, out);
    k_fw<<<1, 1024>>>(E, out);
}

// round 3
// speedup vs baseline: 1.6793x; 1.3183x over previous
#include <cuda_runtime.h>
#include <math.h>

#define V  50257
#define H  1024
#define L  2048
#define ML 2048
#define NRED 52

typedef unsigned long long ull;

// ---------------- scratch (device globals; no allocations allowed) ----------------
__device__ float g_attn_logits[ML];
__device__ float g_attn_weights[ML];
__device__ float g_attn_applied[H];
__device__ float g_rnn_in[H];
__device__ float g_gi[3 * H];
__device__ float g_gh[3 * H];
__device__ float g_hnew[H];
__device__ float g_score_g[V];
__device__ float g_score_c[L];
__device__ float g_bmax[NRED];
__device__ float g_bsum[NRED];
__device__ float g_smax;
__device__ float g_sinv;

// ---------------- helpers ----------------
__device__ __forceinline__ void ffma2(ull& d, ull a, ull b) {
    asm("fma.rn.f32x2 %0, %1, %2, %0;" : "+l"(d) : "l"(a), "l"(b));
}
__device__ __forceinline__ ull pack2(float lo, float hi) {
    ull r; asm("mov.b64 %0, {%1, %2};" : "=l"(r) : "f"(lo), "f"(hi)); return r;
}
__device__ __forceinline__ void unpack2(ull v, float& lo, float& hi) {
    asm("mov.b64 {%0, %1}, %2;" : "=f"(lo), "=f"(hi) : "l"(v));
}

__device__ __forceinline__ float block_reduce_max(float v, float* sred) {
    #pragma unroll
    for (int o = 16; o; o >>= 1) v = fmaxf(v, __shfl_xor_sync(0xffffffffu, v, o));
    int w = threadIdx.x >> 5;
    if ((threadIdx.x & 31) == 0) sred[w] = v;
    __syncthreads();
    int nw = (blockDim.x + 31) >> 5;
    if (threadIdx.x < 32) {
        float x = (threadIdx.x < nw) ? sred[threadIdx.x] : -1e30f;
        #pragma unroll
        for (int o = 16; o; o >>= 1) x = fmaxf(x, __shfl_xor_sync(0xffffffffu, x, o));
        if (threadIdx.x == 0) sred[0] = x;
    }
    __syncthreads();
    float r = sred[0];
    __syncthreads();
    return r;
}

__device__ __forceinline__ float block_reduce_sum(float v, float* sred) {
    #pragma unroll
    for (int o = 16; o; o >>= 1) v += __shfl_xor_sync(0xffffffffu, v, o);
    int w = threadIdx.x >> 5;
    if ((threadIdx.x & 31) == 0) sred[w] = v;
    __syncthreads();
    int nw = (blockDim.x + 31) >> 5;
    if (threadIdx.x < 32) {
        float x = (threadIdx.x < nw) ? sred[threadIdx.x] : 0.f;
        #pragma unroll
        for (int o = 16; o; o >>= 1) x += __shfl_xor_sync(0xffffffffu, x, o);
        if (threadIdx.x == 0) sred[0] = x;
    }
    __syncthreads();
    float r = sred[0];
    __syncthreads();
    return r;
}

__device__ __forceinline__ float warp_reduce_sum(float v) {
    #pragma unroll
    for (int o = 16; o; o >>= 1) v += __shfl_down_sync(0xffffffffu, v, o);
    return v;
}

// ---------------- kernels ----------------

__global__ void k_init() {
    int i = blockIdx.x * blockDim.x + threadIdx.x;
    if (i < H) g_attn_applied[i] = 0.f;
    if (i < L) g_score_c[i] = 0.f;
}

// attn_logits[m] = [emb0, h0] . W_attn_w[m] + b_attn_w[m]
__global__ void k_attn_logits(const int* __restrict__ din_p,
                              const float* __restrict__ emb,
                              const float* __restrict__ h0,
                              const float* __restrict__ Ww,
                              const float* __restrict__ bw) {
    int row  = (blockIdx.x * blockDim.x + threadIdx.x) >> 5;
    int lane = threadIdx.x & 31;
    if (row >= ML) return;
    const float4* w4 = (const float4*)(Ww + (size_t)row * (2 * H));
    const float4* e4 = (const float4*)(emb + (size_t)din_p[0] * H);
    const float4* h4 = (const float4*)h0;
    float acc = 0.f;
    #pragma unroll
    for (int q = lane; q < 256; q += 32) {
        float4 a = w4[q]; float4 x = e4[q];
        acc += a.x * x.x + a.y * x.y + a.z * x.z + a.w * x.w;
    }
    #pragma unroll
    for (int q = lane; q < 256; q += 32) {
        float4 a = w4[256 + q]; float4 x = h4[q];
        acc += a.x * x.x + a.y * x.y + a.z * x.z + a.w * x.w;
    }
    acc = warp_reduce_sum(acc);
    if (lane == 0) g_attn_logits[row] = acc + bw[row];
}

// softmax over ML=2048 (one block, 1024 threads)
__global__ void k_softmax_ml() {
    __shared__ float sred[32];
    int t = threadIdx.x;
    float a = g_attn_logits[t];
    float b = g_attn_logits[t + 1024];
    float m = block_reduce_max(fmaxf(a, b), sred);
    float e1 = expf(a - m);
    float e2 = expf(b - m);
    float s = block_reduce_sum(e1 + e2, sred);
    float inv = 1.f / s;
    g_attn_weights[t]        = e1 * inv;
    g_attn_weights[t + 1024] = e2 * inv;
}

// attn_applied[j] += sum over 16 rows: 128 blocks
__global__ void k_attn_applied(const float* __restrict__ E) {
    __shared__ float w[16];
    int r0 = blockIdx.x * 16;
    if (threadIdx.x < 16) w[threadIdx.x] = g_attn_weights[r0 + threadIdx.x];
    __syncthreads();
    int j = threadIdx.x;  // 1024 == H
    float acc = 0.f;
    #pragma unroll
    for (int i = 0; i < 16; i++)
        acc += w[i] * E[(size_t)(r0 + i) * H + j];
    atomicAdd(&g_attn_applied[j], acc);
}

// rnn_in[j] = relu([emb0, attn_applied] . W_attn_u[j] + b_attn_u[j])
__global__ void k_rnn_in(const int* __restrict__ din_p,
                         const float* __restrict__ emb,
                         const float* __restrict__ Wu,
                         const float* __restrict__ bu) {
    int row  = (blockIdx.x * blockDim.x + threadIdx.x) >> 5;
    int lane = threadIdx.x & 31;
    if (row >= H) return;
    const float4* w4 = (const float4*)(Wu + (size_t)row * (2 * H));
    const float4* e4 = (const float4*)(emb + (size_t)din_p[0] * H);
    const float4* a4 = (const float4*)g_attn_applied;
    float acc = 0.f;
    #pragma unroll
    for (int q = lane; q < 256; q += 32) {
        float4 a = w4[q]; float4 x = e4[q];
        acc += a.x * x.x + a.y * x.y + a.z * x.z + a.w * x.w;
    }
    #pragma unroll
    for (int q = lane; q < 256; q += 32) {
        float4 a = w4[256 + q]; float4 x = a4[q];
        acc += a.x * x.x + a.y * x.y + a.z * x.z + a.w * x.w;
    }
    acc = warp_reduce_sum(acc);
    if (lane == 0) g_rnn_in[row] = fmaxf(acc + bu[row], 0.f);
}

// gi = W_ih @ rnn_in + b_ih ; gh = W_hh @ h0 + b_hh
__global__ void k_gi_gh(const float* __restrict__ Wih, const float* __restrict__ bih,
                        const float* __restrict__ Whh, const float* __restrict__ bhh,
                        const float* __restrict__ h0) {
    int g    = (blockIdx.x * blockDim.x + threadIdx.x) >> 5;
    int lane = threadIdx.x & 31;
    if (g >= 6 * H) return;
    const float4* w4;
    const float4* x4;
    float bb;
    float* outp;
    if (g < 3 * H) {
        w4 = (const float4*)(Wih + (size_t)g * H);
        x4 = (const float4*)g_rnn_in;
        bb = bih[g];
        outp = &g_gi[g];
    } else {
        int r = g - 3 * H;
        w4 = (const float4*)(Whh + (size_t)r * H);
        x4 = (const float4*)h0;
        bb = bhh[r];
        outp = &g_gh[r];
    }
    float acc = 0.f;
    #pragma unroll
    for (int q = lane; q < 256; q += 32) {
        float4 a = w4[q]; float4 x = x4[q];
        acc += a.x * x.x + a.y * x.y + a.z * x.z + a.w * x.w;
    }
    acc = warp_reduce_sum(acc);
    if (lane == 0) *outp = acc + bb;
}

// GRU combine; writes h_new and final_hidden
__global__ void k_gru(const float* __restrict__ h0, float* __restrict__ out) {
    int t = threadIdx.x;
    float r = 1.f / (1.f + expf(-(g_gi[t] + g_gh[t])));
    float z = 1.f / (1.f + expf(-(g_gi[H + t] + g_gh[H + t])));
    float n = tanhf(g_gi[2 * H + t] + r * g_gh[2 * H + t]);
    float h = (1.f - z) * n + z * h0[t];
    g_hnew[t] = h;
    out[V + t] = h;
}

// score_g[v] = h_new . W_gen[v] + b_gen[v]  — 206 MB stream, warp per row
__global__ void k_score_g(const float* __restrict__ Wg, const float* __restrict__ bg) {
    int row  = (blockIdx.x * blockDim.x + threadIdx.x) >> 5;
    int lane = threadIdx.x & 31;
    if (row >= V) return;
    const float4* w4 = (const float4*)(Wg + (size_t)row * H);
    const float4* h4 = (const float4*)g_hnew;
    float acc = 0.f;
    #pragma unroll
    for (int q = lane; q < 256; q += 32) {
        float4 a = w4[q]; float4 x = h4[q];
        acc += a.x * x.x + a.y * x.y + a.z * x.z + a.w * x.w;
    }
    acc = warp_reduce_sum(acc);
    if (lane == 0) g_score_g[row] = acc + bg[row];
}

// score_c: NT SGEMM (f32x2), double-buffered, fused tanh*h0 epilogue
__global__ __launch_bounds__(256) void k_score_c_gemm(
    const float* __restrict__ A,     // E: 2048 x 1024
    const float* __restrict__ B,     // W_copy: 1024 x 1024
    const float* __restrict__ bias,  // b_copy
    const float* __restrict__ h0) {
    const int BK = 16;
    __shared__ float As[2][BK][128];
    __shared__ float Bs[2][BK][128];
    int tid = threadIdx.x;
    int tx = tid & 15;
    int ty = tid >> 4;
    int rowBase = blockIdx.y * 128;
    int colBase = blockIdx.x * 128;

    ull acc[8][4];
    #pragma unroll
    for (int i = 0; i < 8; i++)
        #pragma unroll
        for (int jj = 0; jj < 4; jj++) acc[i][jj] = 0ull;

    int ld_r[2], ld_kq[2];
    #pragma unroll
    for (int p = 0; p < 2; p++) {
        int idx = tid + p * 256;
        ld_r[p]  = idx >> 2;
        ld_kq[p] = idx & 3;
    }

    float4 pa[2], pb[2];
    #pragma unroll
    for (int p = 0; p < 2; p++) {
        pa[p] = *(const float4*)(A + (size_t)(rowBase + ld_r[p]) * 1024 + ld_kq[p] * 4);
        pb[p] = *(const float4*)(B + (size_t)(colBase + ld_r[p]) * 1024 + ld_kq[p] * 4);
    }
    #pragma unroll
    for (int p = 0; p < 2; p++) {
        As[0][ld_kq[p] * 4 + 0][ld_r[p]] = pa[p].x;
        As[0][ld_kq[p] * 4 + 1][ld_r[p]] = pa[p].y;
        As[0][ld_kq[p] * 4 + 2][ld_r[p]] = pa[p].z;
        As[0][ld_kq[p] * 4 + 3][ld_r[p]] = pa[p].w;
        Bs[0][ld_kq[p] * 4 + 0][ld_r[p]] = pb[p].x;
        Bs[0][ld_kq[p] * 4 + 1][ld_r[p]] = pb[p].y;
        Bs[0][ld_kq[p] * 4 + 2][ld_r[p]] = pb[p].z;
        Bs[0][ld_kq[p] * 4 + 3][ld_r[p]] = pb[p].w;
    }
    __syncthreads();

    for (int t = 0; t < 64; t++) {
        int cur = t & 1;
        if (t < 63) {
            int kt = (t + 1) * BK;
            #pragma unroll
            for (int p = 0; p < 2; p++) {
                pa[p] = *(const float4*)(A + (size_t)(rowBase + ld_r[p]) * 1024 + kt + ld_kq[p] * 4);
                pb[p] = *(const float4*)(B + (size_t)(colBase + ld_r[p]) * 1024 + kt + ld_kq[p] * 4);
            }
        }
        #pragma unroll
        for (int kk = 0; kk < BK; kk++) {
            ull ad[8];
            #pragma unroll
            for (int i = 0; i < 8; i++) {
                float av = As[cur][kk][ty * 8 + i];
                ad[i] = pack2(av, av);
            }
            ull b2[4];
            #pragma unroll
            for (int jj = 0; jj < 4; jj++)
                b2[jj] = *(const ull*)&Bs[cur][kk][tx * 8 + jj * 2];
            #pragma unroll
            for (int i = 0; i < 8; i++)
                #pragma unroll
                for (int jj = 0; jj < 4; jj++)
                    ffma2(acc[i][jj], ad[i], b2[jj]);
        }
        if (t < 63) {
            int nb = 1 - cur;
            #pragma unroll
            for (int p = 0; p < 2; p++) {
                As[nb][ld_kq[p] * 4 + 0][ld_r[p]] = pa[p].x;
                As[nb][ld_kq[p] * 4 + 1][ld_r[p]] = pa[p].y;
                As[nb][ld_kq[p] * 4 + 2][ld_r[p]] = pa[p].z;
                As[nb][ld_kq[p] * 4 + 3][ld_r[p]] = pa[p].w;
                Bs[nb][ld_kq[p] * 4 + 0][ld_r[p]] = pb[p].x;
                Bs[nb][ld_kq[p] * 4 + 1][ld_r[p]] = pb[p].y;
                Bs[nb][ld_kq[p] * 4 + 2][ld_r[p]] = pb[p].z;
                Bs[nb][ld_kq[p] * 4 + 3][ld_r[p]] = pb[p].w;
            }
            __syncthreads();
        }
    }

    __shared__ float red[128][17];
    float hv[8], bv[8];
    #pragma unroll
    for (int j = 0; j < 8; j++) {
        int c = colBase + tx * 8 + j;
        hv[j] = h0[c];
        bv[j] = bias[c];
    }
    #pragma unroll
    for (int i = 0; i < 8; i++) {
        float s = 0.f;
        #pragma unroll
        for (int jj = 0; jj < 4; jj++) {
            float lo, hi;
            unpack2(acc[i][jj], lo, hi);
            s += tanhf(lo + bv[jj * 2])     * hv[jj * 2];
            s += tanhf(hi + bv[jj * 2 + 1]) * hv[jj * 2 + 1];
        }
        red[ty * 8 + i][tx] = s;
    }
    __syncthreads();
    if (tid < 128) {
        float s = 0.f;
        #pragma unroll
        for (int x = 0; x < 16; x++) s += red[tid][x];
        atomicAdd(&g_score_c[rowBase + tid], s);
    }
}

// single-pass per-block (max, rescaled expsum) over concat(score_g, score_c)
__global__ void k_redpass() {
    __shared__ float sred[32];
    int x = blockIdx.x * blockDim.x + threadIdx.x;
    float v = -1e30f;
    bool valid = (x < V + L);
    if (valid) v = (x < V) ? g_score_g[x] : g_score_c[x - V];
    float m = block_reduce_max(v, sred);
    float s = valid ? expf(v - m) : 0.f;
    s = block_reduce_sum(s, sred);
    if (threadIdx.x == 0) { g_bmax[blockIdx.x] = m; g_bsum[blockIdx.x] = s; }
}

// combine NRED partials
__global__ void k_redfin() {
    __shared__ float sm[64], ss[64];
    int t = threadIdx.x;
    float m = (t < NRED) ? g_bmax[t] : -1e30f;
    sm[t] = m;
    __syncthreads();
    for (int o = 32; o; o >>= 1) { if (t < o) sm[t] = fmaxf(sm[t], sm[t + o]); __syncthreads(); }
    float M = sm[0];
    float s = (t < NRED) ? g_bsum[t] * expf(g_bmax[t] - M) : 0.f;
    ss[t] = s;
    __syncthreads();
    for (int o = 32; o; o >>= 1) { if (t < o) ss[t] += ss[t + o]; __syncthreads(); }
    if (t == 0) { g_smax = M; g_sinv = 1.f / ss[0]; }
}

// final_output[v] = prob_g[v]; also zero the final_weights region
__global__ void k_out_g(float* __restrict__ out) {
    int i = blockIdx.x * blockDim.x + threadIdx.x;
    if (i < H) out[V + H + i] = 0.f;
    if (i >= V) return;
    out[i] = expf(g_score_g[i] - g_smax) * g_sinv;
}

// prob_c scatter-add into final_output; matched rows -> final_weights directly
__global__ void k_out_c(const int* __restrict__ iv, const int* __restrict__ din_p,
                        const float* __restrict__ E, float* __restrict__ out) {
    int i = blockIdx.x * blockDim.x + threadIdx.x;
    if (i >= L) return;
    float pc = expf(g_score_c[i] - g_smax) * g_sinv;
    int id = iv[i];
    atomicAdd(&out[id], pc);
    if (id == din_p[0]) {
        const float* Er = E + (size_t)i * H;
        float* fw = out + V + H;
        for (int j = 0; j < H; j++) atomicAdd(&fw[j], pc * Er[j]);
    }
}

// ---------------- launcher ----------------
extern "C" void kernel_launch(void* const* d_in, const int* in_sizes, int n_in,
                              void* d_out, int out_size) {
    const int*   din  = (const int*)d_in[0];
    const float* h0   = (const float*)d_in[1];
    const float* E    = (const float*)d_in[2];
    const int*   iv   = (const int*)d_in[3];
    const float* emb  = (const float*)d_in[4];
    const float* Ww   = (const float*)d_in[5];
    const float* bw   = (const float*)d_in[6];
    const float* Wu   = (const float*)d_in[7];
    const float* bu   = (const float*)d_in[8];
    const float* Wih  = (const float*)d_in[9];
    const float* bih  = (const float*)d_in[10];
    const float* Whh  = (const float*)d_in[11];
    const float* bhh  = (const float*)d_in[12];
    const float* Wc   = (const float*)d_in[13];
    const float* bc   = (const float*)d_in[14];
    const float* Wg   = (const float*)d_in[15];
    const float* bg   = (const float*)d_in[16];
    float* out = (float*)d_out;

    static cudaStream_t s2 = nullptr;
    static cudaEvent_t evFork = nullptr, evJoin = nullptr;
    if (s2 == nullptr) {
        cudaStreamCreateWithFlags(&s2, cudaStreamNonBlocking);
        cudaEventCreateWithFlags(&evFork, cudaEventDisableTiming);
        cudaEventCreateWithFlags(&evJoin, cudaEventDisableTiming);
    }

    k_init<<<8, 256>>>();

    // fork: score_c GEMM on side stream (independent of the GRU chain)
    cudaEventRecord(evFork, 0);
    cudaStreamWaitEvent(s2, evFork, 0);
    {
        dim3 grid(1024 / 128, 2048 / 128);  // (8, 16)
        k_score_c_gemm<<<grid, 256, 0, s2>>>(E, Wc, bc, h0);
    }
    cudaEventRecord(evJoin, s2);

    // main chain
    k_attn_logits<<<(ML * 32) / 256, 256>>>(din, emb, h0, Ww, bw);
    k_softmax_ml<<<1, 1024>>>();
    k_attn_applied<<<128, 1024>>>(E);
    k_rnn_in<<<(H * 32) / 256, 256>>>(din, emb, Wu, bu);
    k_gi_gh<<<(6 * H * 32) / 256, 256>>>(Wih, bih, Whh, bhh, h0);
    k_gru<<<1, 1024>>>(h0, out);
    k_score_g<<<(V + 7) / 8, 256>>>(Wg, bg);

    // join: softmax over concat needs both score_g and score_c
    cudaStreamWaitEvent(0, evJoin, 0);
    k_redpass<<<NRED, 1024>>>();
    k_redfin<<<1, 64>>>();
    k_out_g<<<(V + 255) / 256, 256>>>(out);
    k_out_c<<<L / 256, 256>>>(iv, din, E, out);
}

// round 4
// speedup vs baseline: 2.8286x; 1.6844x over previous
#include <cuda_runtime.h>
#include <cuda_bf16.h>
#include <math.h>
#include <stdint.h>

#define V  50257
#define H  1024
#define L  2048
#define ML 2048
#define NRED 52

typedef unsigned long long ull;

// ---------------- scratch (device globals; no allocations allowed) ----------------
__device__ float g_attn_logits[ML];
__device__ float g_attn_applied[H];
__device__ float g_rnn_in[H];
__device__ float g_gi[3 * H];
__device__ float g_gh[3 * H];
__device__ float g_hnew[H];
__device__ float g_score_g[V];
__device__ float g_score_c[L];
__device__ float g_bmax[NRED];
__device__ float g_bsum[NRED];
__device__ float g_smax;
__device__ float g_sinv;
// split-bf16 copies of E and W_copy
__device__ __nv_bfloat16 g_Eh[L * H];
__device__ __nv_bfloat16 g_El[L * H];
__device__ __nv_bfloat16 g_Wh[H * H];
__device__ __nv_bfloat16 g_Wl[H * H];

// ---------------- helpers ----------------
__device__ __forceinline__ float block_reduce_max(float v, float* sred) {
    #pragma unroll
    for (int o = 16; o; o >>= 1) v = fmaxf(v, __shfl_xor_sync(0xffffffffu, v, o));
    int w = threadIdx.x >> 5;
    if ((threadIdx.x & 31) == 0) sred[w] = v;
    __syncthreads();
    int nw = (blockDim.x + 31) >> 5;
    if (threadIdx.x < 32) {
        float x = (threadIdx.x < nw) ? sred[threadIdx.x] : -1e30f;
        #pragma unroll
        for (int o = 16; o; o >>= 1) x = fmaxf(x, __shfl_xor_sync(0xffffffffu, x, o));
        if (threadIdx.x == 0) sred[0] = x;
    }
    __syncthreads();
    float r = sred[0];
    __syncthreads();
    return r;
}

__device__ __forceinline__ float block_reduce_sum(float v, float* sred) {
    #pragma unroll
    for (int o = 16; o; o >>= 1) v += __shfl_xor_sync(0xffffffffu, v, o);
    int w = threadIdx.x >> 5;
    if ((threadIdx.x & 31) == 0) sred[w] = v;
    __syncthreads();
    int nw = (blockDim.x + 31) >> 5;
    if (threadIdx.x < 32) {
        float x = (threadIdx.x < nw) ? sred[threadIdx.x] : 0.f;
        #pragma unroll
        for (int o = 16; o; o >>= 1) x += __shfl_xor_sync(0xffffffffu, x, o);
        if (threadIdx.x == 0) sred[0] = x;
    }
    __syncthreads();
    float r = sred[0];
    __syncthreads();
    return r;
}

__device__ __forceinline__ float warp_reduce_sum(float v) {
    #pragma unroll
    for (int o = 16; o; o >>= 1) v += __shfl_down_sync(0xffffffffu, v, o);
    return v;
}

__device__ __forceinline__ uint32_t smem_u32(const void* p) {
    return (uint32_t)__cvta_generic_to_shared(p);
}
__device__ __forceinline__ void ldsm_x4(uint32_t* r, uint32_t addr) {
    asm volatile("ldmatrix.sync.aligned.m8n8.x4.shared.b16 {%0,%1,%2,%3}, [%4];"
        : "=r"(r[0]), "=r"(r[1]), "=r"(r[2]), "=r"(r[3]) : "r"(addr));
}
__device__ __forceinline__ void ldsm_x2(uint32_t* r, uint32_t addr) {
    asm volatile("ldmatrix.sync.aligned.m8n8.x2.shared.b16 {%0,%1}, [%2];"
        : "=r"(r[0]), "=r"(r[1]) : "r"(addr));
}
__device__ __forceinline__ void mma_bf16(float* d, const uint32_t* a, const uint32_t* b) {
    asm volatile("mma.sync.aligned.m16n8k16.row.col.f32.bf16.bf16.f32 "
        "{%0,%1,%2,%3}, {%4,%5,%6,%7}, {%8,%9}, {%0,%1,%2,%3};"
        : "+f"(d[0]), "+f"(d[1]), "+f"(d[2]), "+f"(d[3])
        : "r"(a[0]), "r"(a[1]), "r"(a[2]), "r"(a[3]), "r"(b[0]), "r"(b[1]));
}
__device__ __forceinline__ float trunc_hi(float x) {
    return __uint_as_float(__float_as_uint(x) & 0xffff0000u);
}

// ---------------- kernels ----------------

__global__ void k_init() {
    int i = blockIdx.x * blockDim.x + threadIdx.x;
    if (i < H) g_attn_applied[i] = 0.f;
    if (i < L) g_score_c[i] = 0.f;
}

// split E and W_copy into bf16 hi/lo (exact: hi = truncate-to-bf16, lo = rn(x - hi))
__global__ void k_split(const float* __restrict__ E, const float* __restrict__ W) {
    const int NE4 = (L * H) / 4;   // 524288
    const int NW4 = (H * H) / 4;   // 262144
    int i = blockIdx.x * blockDim.x + threadIdx.x;
    if (i >= NE4 + NW4) return;
    const float4* src;
    __nv_bfloat162 *dh, *dl;
    int b;
    if (i < NE4) {
        src = (const float4*)E; dh = (__nv_bfloat162*)g_Eh; dl = (__nv_bfloat162*)g_El; b = i;
    } else {
        src = (const float4*)W; dh = (__nv_bfloat162*)g_Wh; dl = (__nv_bfloat162*)g_Wl; b = i - NE4;
    }
    float4 v = src[b];
    float hx = trunc_hi(v.x), hy = trunc_hi(v.y), hz = trunc_hi(v.z), hw = trunc_hi(v.w);
    dh[2 * b + 0] = __floats2bfloat162_rn(hx, hy);
    dh[2 * b + 1] = __floats2bfloat162_rn(hz, hw);
    dl[2 * b + 0] = __floats2bfloat162_rn(v.x - hx, v.y - hy);
    dl[2 * b + 1] = __floats2bfloat162_rn(v.z - hz, v.w - hw);
}

// attn_logits[m] = [emb0, h0] . W_attn_w[m] + b_attn_w[m]
__global__ void k_attn_logits(const int* __restrict__ din_p,
                              const float* __restrict__ emb,
                              const float* __restrict__ h0,
                              const float* __restrict__ Ww,
                              const float* __restrict__ bw) {
    int row  = (blockIdx.x * blockDim.x + threadIdx.x) >> 5;
    int lane = threadIdx.x & 31;
    if (row >= ML) return;
    const float4* w4 = (const float4*)(Ww + (size_t)row * (2 * H));
    const float4* e4 = (const float4*)(emb + (size_t)din_p[0] * H);
    const float4* h4 = (const float4*)h0;
    float acc = 0.f;
    #pragma unroll
    for (int q = lane; q < 256; q += 32) {
        float4 a = w4[q]; float4 x = e4[q];
        acc += a.x * x.x + a.y * x.y + a.z * x.z + a.w * x.w;
    }
    #pragma unroll
    for (int q = lane; q < 256; q += 32) {
        float4 a = w4[256 + q]; float4 x = h4[q];
        acc += a.x * x.x + a.y * x.y + a.z * x.z + a.w * x.w;
    }
    acc = warp_reduce_sum(acc);
    if (lane == 0) g_attn_logits[row] = acc + bw[row];
}

// fused softmax(ML) + attn_applied: each block redundantly reduces the logits,
// then accumulates 16 rows of E weighted by its softmax weights.
__global__ void k_attn_applied(const float* __restrict__ E) {
    __shared__ float sred[32];
    __shared__ float w[16];
    int t = threadIdx.x;
    float a = g_attn_logits[t];
    float b = g_attn_logits[t + 1024];
    float m = block_reduce_max(fmaxf(a, b), sred);
    float s = block_reduce_sum(expf(a - m) + expf(b - m), sred);
    float inv = 1.f / s;
    int r0 = blockIdx.x * 16;
    if (t < 16) w[t] = expf(g_attn_logits[r0 + t] - m) * inv;
    __syncthreads();
    float acc = 0.f;
    #pragma unroll
    for (int i = 0; i < 16; i++)
        acc += w[i] * E[(size_t)(r0 + i) * H + t];
    atomicAdd(&g_attn_applied[t], acc);
}

// rnn_in[j] = relu([emb0, attn_applied] . W_attn_u[j] + b_attn_u[j])
__global__ void k_rnn_in(const int* __restrict__ din_p,
                         const float* __restrict__ emb,
                         const float* __restrict__ Wu,
                         const float* __restrict__ bu) {
    int row  = (blockIdx.x * blockDim.x + threadIdx.x) >> 5;
    int lane = threadIdx.x & 31;
    if (row >= H) return;
    const float4* w4 = (const float4*)(Wu + (size_t)row * (2 * H));
    const float4* e4 = (const float4*)(emb + (size_t)din_p[0] * H);
    const float4* a4 = (const float4*)g_attn_applied;
    float acc = 0.f;
    #pragma unroll
    for (int q = lane; q < 256; q += 32) {
        float4 a = w4[q]; float4 x = e4[q];
        acc += a.x * x.x + a.y * x.y + a.z * x.z + a.w * x.w;
    }
    #pragma unroll
    for (int q = lane; q < 256; q += 32) {
        float4 a = w4[256 + q]; float4 x = a4[q];
        acc += a.x * x.x + a.y * x.y + a.z * x.z + a.w * x.w;
    }
    acc = warp_reduce_sum(acc);
    if (lane == 0) g_rnn_in[row] = fmaxf(acc + bu[row], 0.f);
}

// gh = W_hh @ h0 + b_hh  (independent of the attn chain; forked early)
__global__ void k_gh(const float* __restrict__ Whh, const float* __restrict__ bhh,
                     const float* __restrict__ h0) {
    int g    = (blockIdx.x * blockDim.x + threadIdx.x) >> 5;
    int lane = threadIdx.x & 31;
    if (g >= 3 * H) return;
    const float4* w4 = (const float4*)(Whh + (size_t)g * H);
    const float4* x4 = (const float4*)h0;
    float acc = 0.f;
    #pragma unroll
    for (int q = lane; q < 256; q += 32) {
        float4 a = w4[q]; float4 x = x4[q];
        acc += a.x * x.x + a.y * x.y + a.z * x.z + a.w * x.w;
    }
    acc = warp_reduce_sum(acc);
    if (lane == 0) g_gh[g] = acc + bhh[g];
}

// gi = W_ih @ rnn_in + b_ih
__global__ void k_gi(const float* __restrict__ Wih, const float* __restrict__ bih) {
    int g    = (blockIdx.x * blockDim.x + threadIdx.x) >> 5;
    int lane = threadIdx.x & 31;
    if (g >= 3 * H) return;
    const float4* w4 = (const float4*)(Wih + (size_t)g * H);
    const float4* x4 = (const float4*)g_rnn_in;
    float acc = 0.f;
    #pragma unroll
    for (int q = lane; q < 256; q += 32) {
        float4 a = w4[q]; float4 x = x4[q];
        acc += a.x * x.x + a.y * x.y + a.z * x.z + a.w * x.w;
    }
    acc = warp_reduce_sum(acc);
    if (lane == 0) g_gi[g] = acc + bih[g];
}

// GRU combine; writes h_new and final_hidden
__global__ void k_gru(const float* __restrict__ h0, float* __restrict__ out) {
    int t = threadIdx.x;
    float r = 1.f / (1.f + expf(-(g_gi[t] + g_gh[t])));
    float z = 1.f / (1.f + expf(-(g_gi[H + t] + g_gh[H + t])));
    float n = tanhf(g_gi[2 * H + t] + r * g_gh[2 * H + t]);
    float h = (1.f - z) * n + z * h0[t];
    g_hnew[t] = h;
    out[V + t] = h;
}

// score_g[v] = h_new . W_gen[v] + b_gen[v]  — 206 MB stream, warp per row
__global__ void k_score_g(const float* __restrict__ Wg, const float* __restrict__ bg) {
    int row  = (blockIdx.x * blockDim.x + threadIdx.x) >> 5;
    int lane = threadIdx.x & 31;
    if (row >= V) return;
    const float4* w4 = (const float4*)(Wg + (size_t)row * H);
    const float4* h4 = (const float4*)g_hnew;
    float acc = 0.f;
    #pragma unroll
    for (int q = lane; q < 256; q += 32) {
        float4 a = w4[q]; float4 x = h4[q];
        acc += a.x * x.x + a.y * x.y + a.z * x.z + a.w * x.w;
    }
    acc = warp_reduce_sum(acc);
    if (lane == 0) g_score_g[row] = acc + bg[row];
}

// score_c via split-bf16 tensor-core GEMM:
// S = E @ W_copy.T (fp32-accurate via Ah*Bh + Ah*Bl + Al*Bh), then
// score_c[i] += sum_j tanh(S[i][j] + bias[j]) * h0[j].
// CTA tile 128x128, K-tile 32, 8 warps (2x4), warp tile 64x32, m16n8k16.
#define SAB 40   // padded smem row stride in bf16 units (80 bytes)
__global__ __launch_bounds__(256) void k_score_c_mma(
    const float* __restrict__ bias, const float* __restrict__ h0) {
    __shared__ __nv_bfloat16 sAh[128 * SAB], sAl[128 * SAB];
    __shared__ __nv_bfloat16 sBh[128 * SAB], sBl[128 * SAB];
    int tid  = threadIdx.x;
    int lane = tid & 31;
    int wid  = tid >> 5;
    int wm   = wid >> 2;   // 0..1
    int wn   = wid & 3;    // 0..3
    int rowBase = blockIdx.y * 128;
    int colBase = blockIdx.x * 128;

    float acc[4][4][4];
    #pragma unroll
    for (int mf = 0; mf < 4; mf++)
        #pragma unroll
        for (int nf = 0; nf < 4; nf++)
            #pragma unroll
            for (int r = 0; r < 4; r++) acc[mf][nf][r] = 0.f;

    int lr   = tid >> 2;   // 0..63
    int lseg = tid & 3;    // 0..3 (16B segment within 64B row)

    uint4 vah[2], valo[2], vbh[2], vblo[2];
    #pragma unroll
    for (int p = 0; p < 2; p++) {
        int ra = lr + p * 64;
        size_t offA = ((size_t)(rowBase + ra) << 10) + lseg * 8;
        size_t offB = ((size_t)(colBase + ra) << 10) + lseg * 8;
        vah[p]  = *(const uint4*)(g_Eh + offA);
        valo[p] = *(const uint4*)(g_El + offA);
        vbh[p]  = *(const uint4*)(g_Wh + offB);
        vblo[p] = *(const uint4*)(g_Wl + offB);
    }

    for (int kt = 0; kt < 1024; kt += 32) {
        #pragma unroll
        for (int p = 0; p < 2; p++) {
            int ra = lr + p * 64;
            *(uint4*)&sAh[ra * SAB + lseg * 8] = vah[p];
            *(uint4*)&sAl[ra * SAB + lseg * 8] = valo[p];
            *(uint4*)&sBh[ra * SAB + lseg * 8] = vbh[p];
            *(uint4*)&sBl[ra * SAB + lseg * 8] = vblo[p];
        }
        __syncthreads();
        if (kt + 32 < 1024) {
            #pragma unroll
            for (int p = 0; p < 2; p++) {
                int ra = lr + p * 64;
                size_t offA = ((size_t)(rowBase + ra) << 10) + kt + 32 + lseg * 8;
                size_t offB = ((size_t)(colBase + ra) << 10) + kt + 32 + lseg * 8;
                vah[p]  = *(const uint4*)(g_Eh + offA);
                valo[p] = *(const uint4*)(g_El + offA);
                vbh[p]  = *(const uint4*)(g_Wh + offB);
                vblo[p] = *(const uint4*)(g_Wl + offB);
            }
        }
        #pragma unroll
        for (int ks = 0; ks < 2; ks++) {
            int kk = ks * 16;
            uint32_t ah[4][4], al[4][4], bh[4][2], bl[4][2];
            int arow = wm * 64 + (lane & 15);
            int akc  = kk + ((lane >> 4) & 1) * 8;
            #pragma unroll
            for (int mf = 0; mf < 4; mf++) {
                ldsm_x4(ah[mf], smem_u32(&sAh[(arow + mf * 16) * SAB + akc]));
                ldsm_x4(al[mf], smem_u32(&sAl[(arow + mf * 16) * SAB + akc]));
            }
            int brow = wn * 32 + (lane & 7);
            int bkc  = kk + ((lane >> 3) & 1) * 8;
            #pragma unroll
            for (int nf = 0; nf < 4; nf++) {
                ldsm_x2(bh[nf], smem_u32(&sBh[(brow + nf * 8) * SAB + bkc]));
                ldsm_x2(bl[nf], smem_u32(&sBl[(brow + nf * 8) * SAB + bkc]));
            }
            #pragma unroll
            for (int mf = 0; mf < 4; mf++)
                #pragma unroll
                for (int nf = 0; nf < 4; nf++) {
                    mma_bf16(acc[mf][nf], ah[mf], bh[nf]);
                    mma_bf16(acc[mf][nf], ah[mf], bl[nf]);
                    mma_bf16(acc[mf][nf], al[mf], bh[nf]);
                }
        }
        __syncthreads();
    }

    // epilogue: tanh + h0-weighted reduce over j; per-row atomicAdd
    int g   = lane >> 2;
    int tig = lane & 3;
    float bj[4][2], hj[4][2];
    #pragma unroll
    for (int nf = 0; nf < 4; nf++) {
        int j0 = colBase + wn * 32 + nf * 8 + tig * 2;
        bj[nf][0] = bias[j0];     bj[nf][1] = bias[j0 + 1];
        hj[nf][0] = h0[j0];       hj[nf][1] = h0[j0 + 1];
    }
    #pragma unroll
    for (int mf = 0; mf < 4; mf++) {
        float s0 = 0.f, s1 = 0.f;
        #pragma unroll
        for (int nf = 0; nf < 4; nf++) {
            s0 += tanhf(acc[mf][nf][0] + bj[nf][0]) * hj[nf][0]
                + tanhf(acc[mf][nf][1] + bj[nf][1]) * hj[nf][1];
            s1 += tanhf(acc[mf][nf][2] + bj[nf][0]) * hj[nf][0]
                + tanhf(acc[mf][nf][3] + bj[nf][1]) * hj[nf][1];
        }
        s0 += __shfl_xor_sync(0xffffffffu, s0, 1);
        s0 += __shfl_xor_sync(0xffffffffu, s0, 2);
        s1 += __shfl_xor_sync(0xffffffffu, s1, 1);
        s1 += __shfl_xor_sync(0xffffffffu, s1, 2);
        if (tig == 0) {
            int r = rowBase + wm * 64 + mf * 16 + g;
            atomicAdd(&g_score_c[r], s0);
            atomicAdd(&g_score_c[r + 8], s1);
        }
    }
}

// single-pass per-block (max, local expsum) over concat(score_g, score_c)
__global__ void k_redpass() {
    __shared__ float sred[32];
    int x = blockIdx.x * blockDim.x + threadIdx.x;
    float v = -1e30f;
    bool valid = (x < V + L);
    if (valid) v = (x < V) ? g_score_g[x] : g_score_c[x - V];
    float m = block_reduce_max(v, sred);
    float s = valid ? expf(v - m) : 0.f;
    s = block_reduce_sum(s, sred);
    if (threadIdx.x == 0) { g_bmax[blockIdx.x] = m; g_bsum[blockIdx.x] = s; }
}

__global__ void k_redfin() {
    __shared__ float sm[64], ss[64];
    int t = threadIdx.x;
    float m = (t < NRED) ? g_bmax[t] : -1e30f;
    sm[t] = m;
    __syncthreads();
    for (int o = 32; o; o >>= 1) { if (t < o) sm[t] = fmaxf(sm[t], sm[t + o]); __syncthreads(); }
    float M = sm[0];
    float s = (t < NRED) ? g_bsum[t] * expf(g_bmax[t] - M) : 0.f;
    ss[t] = s;
    __syncthreads();
    for (int o = 32; o; o >>= 1) { if (t < o) ss[t] += ss[t + o]; __syncthreads(); }
    if (t == 0) { g_smax = M; g_sinv = 1.f / ss[0]; }
}

// final_output[v] = prob_g[v]; zero final_weights region
__global__ void k_out_g(float* __restrict__ out) {
    int i = blockIdx.x * blockDim.x + threadIdx.x;
    if (i < H) out[V + H + i] = 0.f;
    if (i >= V) return;
    out[i] = expf(g_score_g[i] - g_smax) * g_sinv;
}

// prob_c scatter-add; matched rows directly into final_weights
__global__ void k_out_c(const int* __restrict__ iv, const int* __restrict__ din_p,
                        const float* __restrict__ E, float* __restrict__ out) {
    int i = blockIdx.x * blockDim.x + threadIdx.x;
    if (i >= L) return;
    float pc = expf(g_score_c[i] - g_smax) * g_sinv;
    int id = iv[i];
    atomicAdd(&out[id], pc);
    if (id == din_p[0]) {
        const float* Er = E + (size_t)i * H;
        float* fw = out + V + H;
        for (int j = 0; j < H; j++) atomicAdd(&fw[j], pc * Er[j]);
    }
}

// ---------------- launcher ----------------
extern "C" void kernel_launch(void* const* d_in, const int* in_sizes, int n_in,
                              void* d_out, int out_size) {
    const int*   din  = (const int*)d_in[0];
    const float* h0   = (const float*)d_in[1];
    const float* E    = (const float*)d_in[2];
    const int*   iv   = (const int*)d_in[3];
    const float* emb  = (const float*)d_in[4];
    const float* Ww   = (const float*)d_in[5];
    const float* bw   = (const float*)d_in[6];
    const float* Wu   = (const float*)d_in[7];
    const float* bu   = (const float*)d_in[8];
    const float* Wih  = (const float*)d_in[9];
    const float* bih  = (const float*)d_in[10];
    const float* Whh  = (const float*)d_in[11];
    const float* bhh  = (const float*)d_in[12];
    const float* Wc   = (const float*)d_in[13];
    const float* bc   = (const float*)d_in[14];
    const float* Wg   = (const float*)d_in[15];
    const float* bg   = (const float*)d_in[16];
    float* out = (float*)d_out;

    static cudaStream_t s2 = nullptr, s3 = nullptr;
    static cudaEvent_t evF0 = nullptr, evF1 = nullptr, evGh = nullptr, evJoin = nullptr;
    if (s2 == nullptr) {
        cudaStreamCreateWithFlags(&s2, cudaStreamNonBlocking);
        cudaStreamCreateWithFlags(&s3, cudaStreamNonBlocking);
        cudaEventCreateWithFlags(&evF0, cudaEventDisableTiming);
        cudaEventCreateWithFlags(&evF1, cudaEventDisableTiming);
        cudaEventCreateWithFlags(&evGh, cudaEventDisableTiming);
        cudaEventCreateWithFlags(&evJoin, cudaEventDisableTiming);
    }

    // fork gh (depends only on inputs) onto s3 immediately
    cudaEventRecord(evF0, 0);
    cudaStreamWaitEvent(s3, evF0, 0);
    k_gh<<<(3 * H * 32) / 256, 256, 0, s3>>>(Whh, bhh, h0);
    cudaEventRecord(evGh, s3);

    k_init<<<8, 256>>>();

    // fork score_c pipeline (split + tensor-core GEMM) onto s2
    cudaEventRecord(evF1, 0);
    cudaStreamWaitEvent(s2, evF1, 0);
    k_split<<<((L * H + H * H) / 4 + 255) / 256, 256, 0, s2>>>(E, Wc);
    {
        dim3 grid(H / 128, L / 128);  // (8, 16)
        k_score_c_mma<<<grid, 256, 0, s2>>>(bc, h0);
    }
    cudaEventRecord(evJoin, s2);

    // main chain
    k_attn_logits<<<(ML * 32) / 256, 256>>>(din, emb, h0, Ww, bw);
    k_attn_applied<<<128, 1024>>>(E);
    k_rnn_in<<<(H * 32) / 256, 256>>>(din, emb, Wu, bu);
    k_gi<<<(3 * H * 32) / 256, 256>>>(Wih, bih);
    cudaStreamWaitEvent(0, evGh, 0);
    k_gru<<<1, 1024>>>(h0, out);
    k_score_g<<<(V + 7) / 8, 256>>>(Wg, bg);

    // join + tail
    cudaStreamWaitEvent(0, evJoin, 0);
    k_redpass<<<NRED, 1024>>>();
    k_redfin<<<1, 64>>>();
    k_out_g<<<(V + 255) / 256, 256>>>(out);
    k_out_c<<<L / 256, 256>>>(iv, din, E, out);
}